// round 16
// baseline (speedup 1.0000x reference)
#include <cuda_runtime.h>
#include <cstdint>
#include <cstddef>

// Monarch embedding, analytically folded:
//   out[tok][kr*32+o] = (kr&1 == s) ? L[v*16 + kr/2] * R[(kr*32 + c)*32 + o] : 0
//   v = x[tok], k = v/786, s = k>>5, c = k&31.
//
// R16: one token per warp-pair, 64B per thread, straight-line.
// Grid 4096 x 256 thr, 4 tokens/CTA. Warp w: token t = w>>1, parity p = w&1
// (warp-uniform). Lane l: kr = 2*(l>>1)+p, osub = (l&1)*16 floats.
// One warp = all 16 same-parity rows x 128B = half the 4KB token row.
// Per thread: ONE v/786 chain, ONE L scalar (warp = one 64B L line),
// two R v8 loads in the same 128B line, two contiguous STG.256
// (warp store = 2KB fully coalesced). Zero warps: just the two stores.
// vs R11: L-gather LDGs and idiv ALU halved, token-mux gone, regs ~26.

__global__ void __launch_bounds__(256) monarch_embed_kernel(
    const int* __restrict__ x,
    const float* __restrict__ L,
    const float* __restrict__ R,
    float* __restrict__ out)
{
    const int tb  = blockIdx.x << 2;       // 4 tokens per CTA
    const int tid = threadIdx.x;
    const int w   = tid >> 5;
    const int l   = tid & 31;
    const int t   = w >> 1;                // token of this warp-pair (0..3)
    const int p   = w & 1;                 // warp parity (uniform)
    const int i   = l >> 1;                // 0..15 : L column / row pair
    const int kr  = (i << 1) + p;          // 0..31
    const int osub = (l & 1) << 4;         // 0 or 16 floats (64B chunk)

    // One aligned 128-bit broadcast load covers x for all 4 tokens.
    const int4 xv = *reinterpret_cast<const int4*>(x + tb);
    const int v = (t == 0) ? xv.x : (t == 1) ? xv.y : (t == 2) ? xv.z : xv.w;

    const int k = v / 786;
    const int s = k >> 5;
    const int c = k & 31;

    float* ob = out + (size_t)(tb + t) * 1024 + (kr << 5) + osub;

    if (s == p) {                          // warp-uniform branch
        const float lv = __ldg(&L[(size_t)v * 16 + i]);   // warp: one 64B line
        const float* rp = &R[((size_t)((kr << 5) + c) << 5) + osub];

        float q0,q1,q2,q3,q4,q5,q6,q7, w0,w1,w2,w3,w4,w5,w6,w7;
        asm("ld.global.nc.v8.f32 {%0,%1,%2,%3,%4,%5,%6,%7}, [%8];"
            : "=f"(q0), "=f"(q1), "=f"(q2), "=f"(q3),
              "=f"(q4), "=f"(q5), "=f"(q6), "=f"(q7) : "l"(rp));
        asm("ld.global.nc.v8.f32 {%0,%1,%2,%3,%4,%5,%6,%7}, [%8];"
            : "=f"(w0), "=f"(w1), "=f"(w2), "=f"(w3),
              "=f"(w4), "=f"(w5), "=f"(w6), "=f"(w7) : "l"(rp + 8));

        q0*=lv; q1*=lv; q2*=lv; q3*=lv; q4*=lv; q5*=lv; q6*=lv; q7*=lv;
        w0*=lv; w1*=lv; w2*=lv; w3*=lv; w4*=lv; w5*=lv; w6*=lv; w7*=lv;

        asm volatile("st.global.v8.f32 [%0], {%1,%2,%3,%4,%5,%6,%7,%8};"
            :: "l"(ob),
               "f"(q0), "f"(q1), "f"(q2), "f"(q3),
               "f"(q4), "f"(q5), "f"(q6), "f"(q7) : "memory");
        asm volatile("st.global.v8.f32 [%0], {%1,%2,%3,%4,%5,%6,%7,%8};"
            :: "l"(ob + 8),
               "f"(w0), "f"(w1), "f"(w2), "f"(w3),
               "f"(w4), "f"(w5), "f"(w6), "f"(w7) : "memory");
    } else {
        const float z = 0.0f;
        asm volatile("st.global.v8.f32 [%0], {%1,%1,%1,%1,%1,%1,%1,%1};"
            :: "l"(ob), "f"(z) : "memory");
        asm volatile("st.global.v8.f32 [%0], {%1,%1,%1,%1,%1,%1,%1,%1};"
            :: "l"(ob + 8), "f"(z) : "memory");
    }
}

extern "C" void kernel_launch(void* const* d_in, const int* in_sizes, int n_in,
                              void* d_out, int out_size) {
    const int*   x = (const int*)  d_in[0];   // (8, 2048) int32
    const float* L = (const float*)d_in[1];   // (64, 786, 16) f32
    const float* R = (const float*)d_in[2];   // (32, 32, 32) f32
    // d_in[3] = p : analytically folded (perfect_shuffle(64, 1024))

    const int ntok = out_size / 1024;         // 16384 tokens
    monarch_embed_kernel<<<ntok / 4, 256>>>(x, L, R, (float*)d_out);
}